// round 4
// baseline (speedup 1.0000x reference)
#include <cuda_runtime.h>

#define NTOK   4096
#define PDIM   128
#define HEADS  4
#define EDIM   32
#define NSEGS  32
#define KCAP   192     // max keys per segment on the fast path
#define QT     64      // queries per attention block
#define QTILES 3
#define KSTR   192     // KT row stride
#define VSTR   196     // VT row stride (mod 32 = 4 -> 2-way on strided-e loads)
#define SJ     196     // S row stride, query-major (mod 8 = 4 -> 2-way on strided-q loads)
#define QSCALE 0.17677669529663687f
#define NEGINF (-3.0e38f)

__device__ float g_QKV[3][NTOK * PDIM];
__device__ int   g_idx[NTOK];
__device__ int   g_off[NSEGS + 1];
__device__ int   g_cnt[NSEGS];

// f32x2 helpers (sm_103a packed FFMA2, PTX-only)
__device__ __forceinline__ unsigned long long f2pk(float lo, float hi) {
    unsigned long long r;
    asm("mov.b64 %0, {%1, %2};" : "=l"(r) : "f"(lo), "f"(hi));
    return r;
}
__device__ __forceinline__ unsigned long long ffma2(unsigned long long a,
                                                    unsigned long long b,
                                                    unsigned long long c) {
    unsigned long long d;
    asm("fma.rn.f32x2 %0, %1, %2, %3;" : "=l"(d) : "l"(a), "l"(b), "l"(c));
    return d;
}
__device__ __forceinline__ void f2un(unsigned long long v, float& lo, float& hi) {
    asm("mov.b64 {%0, %1}, %2;" : "=f"(lo), "=f"(hi) : "l"(v));
}

// ---------------------------------------------------------------------------
// Fused O(N) stable sort-by-segment (one block, 256 threads)
// ---------------------------------------------------------------------------
__device__ void sort_block(const int* __restrict__ pos, int* sm) {
    int* spos    = sm;            // 4096
    int* hist    = sm + 4096;     // 4096
    int* warptot = sm + 8192;     // 8
    const int tid = threadIdx.x, lane = tid & 31, w = tid >> 5;

    const int4* pos4 = (const int4*)pos;
    int4 z4 = make_int4(0, 0, 0, 0);
    for (int i = tid; i < NTOK / 4; i += 256) {
        ((int4*)spos)[i] = pos4[i];
        ((int4*)hist)[i] = z4;
    }
    __syncthreads();

    for (int g = w; g < 128; g += 8) {
        int s = spos[g * 32 + lane];
        unsigned mask = __match_any_sync(0xffffffffu, s);
        if (lane == __ffs(mask) - 1) hist[s * 128 + g] = __popc(mask);
    }
    __syncthreads();

    int base = tid * 16;
    int loc[16];
    int run = 0;
#pragma unroll
    for (int i = 0; i < 16; i++) { loc[i] = run; run += hist[base + i]; }
    int s = run;
#pragma unroll
    for (int d = 1; d < 32; d <<= 1) {
        int o = __shfl_up_sync(0xffffffffu, s, d);
        if (lane >= d) s += o;
    }
    int excl = s - run;
    if (lane == 31) warptot[w] = s;
    __syncthreads();
    if (tid == 0) {
        int a = 0;
#pragma unroll
        for (int i = 0; i < 8; i++) { int t = warptot[i]; warptot[i] = a; a += t; }
    }
    __syncthreads();
    int offt = warptot[w] + excl;
#pragma unroll
    for (int i = 0; i < 16; i++) hist[base + i] = offt + loc[i];
    __syncthreads();

    if (tid < NSEGS) {
        int o   = hist[tid * 128];
        int nxt = (tid == NSEGS - 1) ? NTOK : hist[(tid + 1) * 128];
        g_off[tid] = o;
        g_cnt[tid] = nxt - o;
        if (tid == 0) g_off[NSEGS] = NTOK;
    }

    for (int g = w; g < 128; g += 8) {
        int tok = g * 32 + lane;
        int sg = spos[tok];
        unsigned mask = __match_any_sync(0xffffffffu, sg);
        int rank = __popc(mask & ((1u << lane) - 1u));
        g_idx[hist[sg * 128 + g] + rank] = tok;
    }
}

// ---------------------------------------------------------------------------
// QKV projection + fused sort. grid (65, 3). 64-row x 128-col tiles.
// Thread tile 4 rows x 8 cols (two strided 4-col groups -> 2-way banks).
// ---------------------------------------------------------------------------
__global__ __launch_bounds__(256)
void qkv_sort_kernel(const float* __restrict__ inp, const int* __restrict__ pos,
                     const float* __restrict__ Wq, const float* __restrict__ bq,
                     const float* __restrict__ Wk, const float* __restrict__ bk,
                     const float* __restrict__ Wv, const float* __restrict__ bv)
{
    extern __shared__ float sm[];
    if (blockIdx.x == 64) {
        if (blockIdx.y == 0) sort_block(pos, (int*)sm);
        return;
    }

    float* As = sm;               // 64 x 128
    float* Bs = sm + 64 * PDIM;   // 128 x 128

    const int which = blockIdx.y;
    const float* W = (which == 0) ? Wq : (which == 1) ? Wk : Wv;
    const float* b = (which == 0) ? bq : (which == 1) ? bk : bv;
    float* outp = g_QKV[which];

    const int row0 = blockIdx.x * 64;
    const int tid = threadIdx.x;

    const float4* inp4 = (const float4*)(inp + row0 * PDIM);
    const float4* W4 = (const float4*)W;
    for (int i = tid; i < 2048; i += 256) ((float4*)As)[i] = inp4[i];
    for (int i = tid; i < 4096; i += 256) ((float4*)Bs)[i] = W4[i];
    __syncthreads();

    const int tx = tid & 15, ty = tid >> 4;   // rows ty*4..+3, cols tx*4..+3 and 64+tx*4..+3

    unsigned long long acc[4][4];
#pragma unroll
    for (int i = 0; i < 4; i++)
#pragma unroll
        for (int p = 0; p < 4; p++) acc[i][p] = 0ull;

#pragma unroll 2
    for (int k0 = 0; k0 < PDIM; k0 += 4) {
        float4 a[4];
#pragma unroll
        for (int i = 0; i < 4; i++)
            a[i] = *(const float4*)&As[(ty * 4 + i) * PDIM + k0];
#pragma unroll
        for (int kk = 0; kk < 4; kk++) {
            const float* Brow = Bs + (k0 + kk) * PDIM;
            ulonglong2 b0 = *(const ulonglong2*)(Brow + tx * 4);
            ulonglong2 b1 = *(const ulonglong2*)(Brow + 64 + tx * 4);
#pragma unroll
            for (int i = 0; i < 4; i++) {
                float av = (kk == 0) ? a[i].x : (kk == 1) ? a[i].y : (kk == 2) ? a[i].z : a[i].w;
                unsigned long long ad = f2pk(av, av);
                acc[i][0] = ffma2(ad, b0.x, acc[i][0]);
                acc[i][1] = ffma2(ad, b0.y, acc[i][1]);
                acc[i][2] = ffma2(ad, b1.x, acc[i][2]);
                acc[i][3] = ffma2(ad, b1.y, acc[i][3]);
            }
        }
    }

    float4 bias0 = *(const float4*)&b[tx * 4];
    float4 bias1 = *(const float4*)&b[64 + tx * 4];
#pragma unroll
    for (int i = 0; i < 4; i++) {
        int row = row0 + ty * 4 + i;
        float x0, x1, x2, x3;
        f2un(acc[i][0], x0, x1); f2un(acc[i][1], x2, x3);
        *(float4*)&outp[row * PDIM + tx * 4] =
            make_float4(x0 + bias0.x, x1 + bias0.y, x2 + bias0.z, x3 + bias0.w);
        f2un(acc[i][2], x0, x1); f2un(acc[i][3], x2, x3);
        *(float4*)&outp[row * PDIM + 64 + tx * 4] =
            make_float4(x0 + bias1.x, x1 + bias1.y, x2 + bias1.z, x3 + bias1.w);
    }
}

// ---------------------------------------------------------------------------
// Attention per (seg, head, 64-query tile). 256 threads, 2 blocks/SM.
// S is query-major [q][SJ]; GEMM pairs run along keys (j) -> no K/V dup-packs.
// SMEM: KT[32][192] VT[32][196] QsT[32][64] S[64][196] sInv[64] = 108288 B
// ---------------------------------------------------------------------------
__global__ __launch_bounds__(256, 2)
void attn_kernel(float* __restrict__ out)
{
    extern __shared__ float smf[];
    float* KT   = smf;                        // 32*KSTR
    float* VT   = KT + EDIM * KSTR;           // 32*VSTR
    float* QsT  = VT + EDIM * VSTR;           // 32*QT
    float* S    = QsT + EDIM * QT;            // QT*SJ
    float* sInv = S + QT * SJ;                // QT

    const int seg = blockIdx.x, h = blockIdx.y, z = blockIdx.z;
    const int off = g_off[seg];
    const int cnt = g_cnt[seg];
    const int tid = threadIdx.x, lane = tid & 31, w = tid >> 5;

    const float* Q = g_QKV[0];
    const float* K = g_QKV[1];
    const float* V = g_QKV[2];

    if (cnt > KCAP) {
        // fallback: streaming online softmax (correct for any count)
        int gw = z * 8 + w;
        for (int qi = gw; qi < cnt; qi += QTILES * 8) {
            int t = g_idx[off + qi];
            float qv = Q[t * PDIM + h * EDIM + lane] * QSCALE;
            float m = NEGINF, l = 0.f, a = 0.f;
            for (int j = 0; j < cnt; j++) {
                int tj = g_idx[off + j];
                float s = qv * K[tj * PDIM + h * EDIM + lane];
#pragma unroll
                for (int d = 16; d; d >>= 1) s += __shfl_xor_sync(0xffffffffu, s, d);
                float mn  = fmaxf(m, s);
                float cor = __expf(m - mn);
                float pj  = __expf(s - mn);
                l = l * cor + pj;
                a = a * cor + pj * V[tj * PDIM + h * EDIM + lane];
                m = mn;
            }
            out[t * PDIM + h * EDIM + lane] = a / l;
        }
        return;
    }

    const int nq = min(QT, cnt - z * QT);
    if (nq <= 0) return;
    const int cnt4 = (cnt + 3) & ~3;

    // gather K -> KT (transposed), V -> VT (transposed)
    for (int i = tid; i < cnt * 8; i += 256) {
        int r = i >> 3, c = i & 7;
        int t = g_idx[off + r];
        float4 kf = *(const float4*)(K + t * PDIM + h * EDIM + c * 4);
        KT[(c * 4 + 0) * KSTR + r] = kf.x;
        KT[(c * 4 + 1) * KSTR + r] = kf.y;
        KT[(c * 4 + 2) * KSTR + r] = kf.z;
        KT[(c * 4 + 3) * KSTR + r] = kf.w;
        float4 vf = *(const float4*)(V + t * PDIM + h * EDIM + c * 4);
        VT[(c * 4 + 0) * VSTR + r] = vf.x;
        VT[(c * 4 + 1) * VSTR + r] = vf.y;
        VT[(c * 4 + 2) * VSTR + r] = vf.z;
        VT[(c * 4 + 3) * VSTR + r] = vf.w;
    }
    // zero tails [cnt, KCAP)
    for (int i = tid; i < (KCAP - cnt) * 8; i += 256) {
        int r = cnt + (i >> 3), c = i & 7;
#pragma unroll
        for (int cc = 0; cc < 4; cc++) {
            KT[(c * 4 + cc) * KSTR + r] = 0.f;
            VT[(c * 4 + cc) * VSTR + r] = 0.f;
        }
    }
    // gather Q tile (transposed, pre-scaled) + zero tail
    for (int i = tid; i < nq * 8; i += 256) {
        int q = i >> 3, c = i & 7;
        int t = g_idx[off + z * QT + q];
        float4 qf = *(const float4*)(Q + t * PDIM + h * EDIM + c * 4);
        QsT[(c * 4 + 0) * QT + q] = qf.x * QSCALE;
        QsT[(c * 4 + 1) * QT + q] = qf.y * QSCALE;
        QsT[(c * 4 + 2) * QT + q] = qf.z * QSCALE;
        QsT[(c * 4 + 3) * QT + q] = qf.w * QSCALE;
    }
    for (int i = tid; i < (QT - nq) * 8; i += 256) {
        int q = nq + (i >> 3), c = i & 7;
#pragma unroll
        for (int cc = 0; cc < 4; cc++) QsT[(c * 4 + cc) * QT + q] = 0.f;
    }
    __syncthreads();

    // ---- GEMM1: S[q][j] = sum_e Q[q][e]*K[j][e], pairs along j ----
    {
        const int tx = tid & 15, ty = tid >> 4;   // keys tx*12..+11, queries ty+{0,16,32,48}
        unsigned long long acc[4][6];
#pragma unroll
        for (int i = 0; i < 4; i++)
#pragma unroll
            for (int p = 0; p < 6; p++) acc[i][p] = 0ull;

#pragma unroll 4
        for (int e = 0; e < EDIM; e++) {
            const float* qe = QsT + e * QT + ty;
            float q0 = qe[0], q1 = qe[16], q2 = qe[32], q3 = qe[48];
            unsigned long long qd[4] = { f2pk(q0, q0), f2pk(q1, q1), f2pk(q2, q2), f2pk(q3, q3) };
            const float* kte = KT + e * KSTR + tx * 12;
            ulonglong2 k0 = *(const ulonglong2*)(kte);
            ulonglong2 k1 = *(const ulonglong2*)(kte + 4);
            ulonglong2 k2 = *(const ulonglong2*)(kte + 8);
#pragma unroll
            for (int i = 0; i < 4; i++) {
                acc[i][0] = ffma2(qd[i], k0.x, acc[i][0]);
                acc[i][1] = ffma2(qd[i], k0.y, acc[i][1]);
                acc[i][2] = ffma2(qd[i], k1.x, acc[i][2]);
                acc[i][3] = ffma2(qd[i], k1.y, acc[i][3]);
                acc[i][4] = ffma2(qd[i], k2.x, acc[i][4]);
                acc[i][5] = ffma2(qd[i], k2.y, acc[i][5]);
            }
        }
#pragma unroll
        for (int i = 0; i < 4; i++) {
            float* srow = S + (ty + 16 * i) * SJ + tx * 12;
#pragma unroll
            for (int p = 0; p < 6; p++)
                *(unsigned long long*)(srow + 2 * p) = acc[i][p];
        }
    }
    __syncthreads();

    // ---- softmax per query row (contiguous float4; tail masked; P tail -> 0) ----
    for (int q = w; q < nq; q += 8) {
        float* srow = S + q * SJ;
        float m = NEGINF;
        for (int j0 = lane * 4; j0 < cnt4; j0 += 128) {
            float4 v = *(const float4*)(srow + j0);
            m = fmaxf(m, (j0 + 0 < cnt) ? v.x : NEGINF);
            m = fmaxf(m, (j0 + 1 < cnt) ? v.y : NEGINF);
            m = fmaxf(m, (j0 + 2 < cnt) ? v.z : NEGINF);
            m = fmaxf(m, (j0 + 3 < cnt) ? v.w : NEGINF);
        }
#pragma unroll
        for (int d = 16; d; d >>= 1) m = fmaxf(m, __shfl_xor_sync(0xffffffffu, m, d));
        float sum = 0.f;
        for (int j0 = lane * 4; j0 < cnt4; j0 += 128) {
            float4 v = *(const float4*)(srow + j0);
            v.x = (j0 + 0 < cnt) ? __expf(v.x - m) : 0.f;
            v.y = (j0 + 1 < cnt) ? __expf(v.y - m) : 0.f;
            v.z = (j0 + 2 < cnt) ? __expf(v.z - m) : 0.f;
            v.w = (j0 + 3 < cnt) ? __expf(v.w - m) : 0.f;
            *(float4*)(srow + j0) = v;
            sum += v.x + v.y + v.z + v.w;
        }
#pragma unroll
        for (int d = 16; d; d >>= 1) sum += __shfl_xor_sync(0xffffffffu, sum, d);
        if (lane == 0) sInv[q] = 1.f / sum;
    }
    __syncthreads();

    // ---- GEMM2: O[q][e] = sum_j P[q][j]*V[j][e], pairs along j ----
    {
        const int tq = tid & 15, te = tid >> 4;   // q = tq+{0,16,32,48}, e = te, te+16
        unsigned long long acc[4][2];
#pragma unroll
        for (int i = 0; i < 4; i++) { acc[i][0] = 0ull; acc[i][1] = 0ull; }

        const float* v0p = VT + te * VSTR;
        const float* v1p = VT + (te + 16) * VSTR;
#pragma unroll 2
        for (int j = 0; j < cnt4; j += 4) {
            ulonglong2 v0 = *(const ulonglong2*)(v0p + j);
            ulonglong2 v1 = *(const ulonglong2*)(v1p + j);
#pragma unroll
            for (int i = 0; i < 4; i++) {
                ulonglong2 p = *(const ulonglong2*)(S + (tq + 16 * i) * SJ + j);
                acc[i][0] = ffma2(p.x, v0.x, acc[i][0]);
                acc[i][0] = ffma2(p.y, v0.y, acc[i][0]);
                acc[i][1] = ffma2(p.x, v1.x, acc[i][1]);
                acc[i][1] = ffma2(p.y, v1.y, acc[i][1]);
            }
        }

#pragma unroll
        for (int i = 0; i < 4; i++) {
            int q = tq + 16 * i;
            if (q < nq) {
                int t = g_idx[off + z * QT + q];
                float iv = sInv[q];
                float lo, hi;
                f2un(acc[i][0], lo, hi);
                out[t * PDIM + h * EDIM + te] = (lo + hi) * iv;
                f2un(acc[i][1], lo, hi);
                out[t * PDIM + h * EDIM + te + 16] = (lo + hi) * iv;
            }
        }
    }
}

// ---------------------------------------------------------------------------
extern "C" void kernel_launch(void* const* d_in, const int* in_sizes, int n_in,
                              void* d_out, int out_size)
{
    const float* inp = (const float*)d_in[0];
    const int*   pos = (const int*)  d_in[1];
    const float* Wq  = (const float*)d_in[2];
    const float* bq  = (const float*)d_in[3];
    const float* Wk  = (const float*)d_in[4];
    const float* bk  = (const float*)d_in[5];
    const float* Wv  = (const float*)d_in[6];
    const float* bv  = (const float*)d_in[7];
    float* out = (float*)d_out;

    const int qkv_smem  = (64 * PDIM + PDIM * PDIM) * 4;                         // 98304
    const int attn_smem = (EDIM * KSTR + EDIM * VSTR + EDIM * QT
                           + QT * SJ + QT) * 4;                                  // 108288

    cudaFuncSetAttribute(qkv_sort_kernel, cudaFuncAttributeMaxDynamicSharedMemorySize, qkv_smem);
    cudaFuncSetAttribute(attn_kernel,     cudaFuncAttributeMaxDynamicSharedMemorySize, attn_smem);

    qkv_sort_kernel<<<dim3(65, 3), 256, qkv_smem>>>(inp, pos, Wq, bq, Wk, bk, Wv, bv);
    attn_kernel<<<dim3(NSEGS, HEADS, QTILES), 256, attn_smem>>>(out);
}